// round 15
// baseline (speedup 1.0000x reference)
#include <cuda_runtime.h>
#include <math.h>

typedef unsigned long long ull;

// ---------------------------------------------------------------------------
// MAPHead: probe-attention pooling + MLP. N=32, L=4096, D=768, H=12, MLP=3072.
//   logits[n,h,l] = x[n,l,:] . wkq[:,h]      (pass 1, f32x2 head pairs, 2-row;
//                                             bk.q const dropped: softmax-inv)
//   k_logits emits per-chunk (m,sumexp)      (fused normalizer, parallel tail)
//   xbar[n,h,:] = sum_l softmax * x[n,l,:]   (pass 2, f32x2, 3 CTAs/SM)
//   o -> xa+LN (fused) -> MLP on [32,768]    (epilogue: 4-batch GEMVs)
// ---------------------------------------------------------------------------

#define NB   32
#define LSEQ 4096
#define DM   768
#define NH   12
#define DH   64
#define MLPD 3072
#define NCH  16                 // 256-row chunks (pass 1 & 2)

__device__ __forceinline__ ull pk2(float a, float b) {
    ull r; asm("mov.b64 %0,{%1,%2};" : "=l"(r) : "f"(a), "f"(b)); return r;
}
__device__ __forceinline__ void up2(ull v, float& a, float& b) {
    asm("mov.b64 {%0,%1},%2;" : "=f"(a), "=f"(b) : "l"(v));
}
__device__ __forceinline__ void fma2(ull& acc, ull a, ull b) {
    asm("fma.rn.f32x2 %0,%1,%2,%0;" : "+l"(acc) : "l"(a), "l"(b));
}
__device__ __forceinline__ ull add2(ull a, ull b) {
    ull r; asm("add.rn.f32x2 %0,%1,%2;" : "=l"(r) : "l"(a), "l"(b)); return r;
}
__device__ __forceinline__ float gelu_f(float a) {
    float u = 0.7978845608028654f * (a + 0.044715f * a * a * a);
    return 0.5f * a * (1.f + tanhf(u));
}

// ------------------------------ scratch -------------------------------------
__device__ float  g_qp[4*DM];                         // probe@wq d-slice partials
__device__ float2 g_wkq2[6*DM];                       // [hp][d] head pairs
__device__ float  g_logits[(size_t)NB*NH*LSEQ];
__device__ float2 g_cms[NB*NCH*NH];                   // per-chunk (m, sumexp)
__device__ ull    g_part[(size_t)NB*NCH*NH*(DM/2)];   // chunk partial xbar
__device__ float  g_xbar[NB*NH*DM];
__device__ float  g_o[NB*NH*DH];
__device__ float  g_xa[NB*DM];
__device__ float  g_y[NB*DM];
__device__ float  g_h1[NB*MLPD];
__device__ float  g_mp[4*NB*DM];                      // mlp2 K-split partials

// ------------------------------ prep 1: qp[s][he] = probe_s . wq_s -----------
// grid 4 (d-slices of 192), block 768 (he). wq[d*768+he]: coalesced.
__global__ void k_qp(const float* __restrict__ probe,
                     const float* __restrict__ wq) {
    __shared__ float ps[192];
    int s = blockIdx.x, t = threadIdx.x;
    if (t < 192) ps[t] = probe[s*192 + t];
    __syncthreads();
    float acc = 0.f;
    const float* wp = wq + (size_t)(s*192)*(NH*DH) + t;
    #pragma unroll 8
    for (int d = 0; d < 192; ++d) acc = fmaf(ps[d], wp[(size_t)d*(NH*DH)], acc);
    g_qp[s*DM + t] = acc;
}

// ------------------------------ prep 2: wkq (qvec fused, head-pair packed) ---
__global__ void prep_wkq(const float* __restrict__ wk, const float* __restrict__ bq) {
    __shared__ float qv[NH*DH];
    int t = threadIdx.x;
    for (int i = t; i < NH*DH; i += 256)
        qv[i] = (g_qp[i] + g_qp[DM + i] + g_qp[2*DM + i] + g_qp[3*DM + i]
                 + bq[i]) * 0.125f;
    __syncthreads();
    int idx = blockIdx.x*256 + t;
    if (idx < NH*DM) {
        int d = idx / NH, h = idx - d*NH;
        float acc = 0.f;
        const float* w = wk + (size_t)d*(NH*DH) + h*DH;
        const float* q = qv + h*DH;
        #pragma unroll
        for (int e = 0; e < DH; ++e) acc = fmaf(w[e], q[e], acc);
        ((float*)g_wkq2)[(((h>>1)*DM) + d)*2 + (h&1)] = acc;
    }
}

// ------------------------------ pass 1: logits + chunk (m,s) -----------------
// grid (NCH, NB), block 256 (8 warps). Warp: 32 rows, 2 at a time (R11-proven).
// Tail: 192 threads (16 per head), shfl-reduced (m, sumexp).
__global__ void __launch_bounds__(256, 4)
k_logits(const float* __restrict__ x) {
    __shared__ float2 wks[6*DM];     // 36 KB
    const int t = threadIdx.x, lane = t & 31, w = t >> 5;
    const int n = blockIdx.y;
    const int row0 = blockIdx.x*256 + w*32;

    for (int i = t; i < 6*DM/2; i += 256)
        ((float4*)wks)[i] = ((const float4*)g_wkq2)[i];
    __syncthreads();

    for (int rb = 0; rb < 32; rb += 2) {
        const float* x0 = x + ((size_t)n*LSEQ + row0 + rb)*DM + lane;
        const float* x1 = x0 + DM;
        ull a0[6], a1[6];
        #pragma unroll
        for (int hp = 0; hp < 6; ++hp) { a0[hp] = 0ULL; a1[hp] = 0ULL; }

        #pragma unroll 4
        for (int j = 0; j < 24; ++j) {
            float u = x0[j*32];
            float v = x1[j*32];
            ull U = pk2(u, u), V = pk2(v, v);
            #pragma unroll
            for (int hp = 0; hp < 6; ++hp) {
                ull wv = *(const ull*)(wks + hp*DM + j*32 + lane);
                fma2(a0[hp], U, wv);
                fma2(a1[hp], V, wv);
            }
        }

        // packed butterfly reduce: 2 SHFL + 1 ADD2 per (hp, step)
        #pragma unroll
        for (int off = 16; off; off >>= 1)
            #pragma unroll
            for (int hp = 0; hp < 6; ++hp) {
                a0[hp] = add2(a0[hp], __shfl_xor_sync(0xffffffffu, a0[hp], off));
                a1[hp] = add2(a1[hp], __shfl_xor_sync(0xffffffffu, a1[hp], off));
            }

        if (lane < 2) {
            int l = row0 + rb + lane;
            float fr[NH];
            #pragma unroll
            for (int hp = 0; hp < 6; ++hp) {
                ull a = (lane == 0) ? a0[hp] : a1[hp];
                up2(a, fr[2*hp], fr[2*hp+1]);
            }
            #pragma unroll
            for (int h = 0; h < NH; ++h)
                g_logits[((size_t)n*NH + h)*LSEQ + l] = fr[h];
        }
    }

    // tail: per-chunk (m, sumexp), 16 threads per head, shfl-reduced
    __syncthreads();
    if (t < 192) {
        int g = t >> 4, i = t & 15;
        const float* lp = g_logits + ((size_t)n*NH + g)*LSEQ + blockIdx.x*256;
        float m = -1e30f;
        #pragma unroll
        for (int k = 0; k < 16; ++k) m = fmaxf(m, lp[i + k*16]);
        #pragma unroll
        for (int off = 8; off; off >>= 1)
            m = fmaxf(m, __shfl_xor_sync(0xffffffffu, m, off));
        float s = 0.f;
        #pragma unroll
        for (int k = 0; k < 16; ++k) s += __expf(lp[i + k*16] - m);
        #pragma unroll
        for (int off = 8; off; off >>= 1)
            s += __shfl_xor_sync(0xffffffffu, s, off);
        if (i == 0)
            g_cms[((size_t)n*NCH + blockIdx.x)*NH + g] = make_float2(m, s);
    }
}

// ------------------------------ pass 2: xbar (3 CTAs/SM target) --------------
__global__ void __launch_bounds__(384, 3)
k_xbar(const float* __restrict__ x) {
    __shared__ ull   p2s[NH*256];    // 24 KB
    __shared__ float Ms[NH], Is[NH];
    const int t = threadIdx.x, s = blockIdx.x, n = blockIdx.y;

    if (t < NH) {
        float M = -1e30f;
        #pragma unroll
        for (int c = 0; c < NCH; ++c)
            M = fmaxf(M, g_cms[((size_t)n*NCH + c)*NH + t].x);
        float S = 0.f;
        #pragma unroll
        for (int c = 0; c < NCH; ++c) {
            float2 ms = g_cms[((size_t)n*NCH + c)*NH + t];
            S += __expf(ms.x - M) * ms.y;
        }
        Ms[t] = M; Is[t] = 1.f / S;
    }
    __syncthreads();

    for (int i = t; i < NH*256; i += 384) {
        int h = i >> 8, r = i & 255;
        float lg = g_logits[((size_t)n*NH + h)*LSEQ + s*256 + r];
        float p = __expf(lg - Ms[h]) * Is[h];
        p2s[i] = pk2(p, p);
    }
    __syncthreads();

    ull acc[NH];
    #pragma unroll
    for (int h = 0; h < NH; ++h) acc[h] = 0ULL;

    const ull* xq = (const ull*)(x + ((size_t)n*LSEQ + s*256)*DM) + t;

    for (int r = 0; r < 256; r += 4) {
        ull x0 = xq[(size_t)(r+0)*(DM/2)];
        ull x1 = xq[(size_t)(r+1)*(DM/2)];
        ull x2 = xq[(size_t)(r+2)*(DM/2)];
        ull x3 = xq[(size_t)(r+3)*(DM/2)];
        #pragma unroll
        for (int h = 0; h < NH; ++h) {
            const ulonglong2* pp = (const ulonglong2*)(p2s + h*256 + r);
            ulonglong2 p01 = pp[0];
            ulonglong2 p23 = pp[1];
            fma2(acc[h], p01.x, x0);
            fma2(acc[h], p01.y, x1);
            fma2(acc[h], p23.x, x2);
            fma2(acc[h], p23.y, x3);
        }
    }
    #pragma unroll
    for (int h = 0; h < NH; ++h)
        g_part[(((size_t)(n*NCH + s)*NH) + h)*(DM/2) + t] = acc[h];
}

// ------------------------------ merge -> xbar[n][h][d] -----------------------
__global__ void k_merge() {
    int h = blockIdx.x, n = blockIdx.y, t = threadIdx.x;
    const float* pf = (const float*)g_part;
    #pragma unroll
    for (int j = 0; j < 3; ++j) {
        int d = j*256 + t;
        float a = 0.f;
        #pragma unroll
        for (int s = 0; s < NCH; ++s)
            a += pf[(((size_t)(n*NCH + s)*NH) + h)*DM + d];
        g_xbar[((size_t)n*NH + h)*DM + d] = a;
    }
}

// ------------------------------ proj1: o = xbar@wv + bv (4-batch) ------------
// grid (3, 8), block 256. Thread: column he, 4 batches.
__global__ void k_proj1(const float* __restrict__ wv, const float* __restrict__ bv) {
    int n0 = blockIdx.y*4;
    int he = blockIdx.x*256 + threadIdx.x;
    int h = he >> 6;
    const float* x0 = g_xbar + ((size_t)(n0*NH) + h)*DM;
    float bvv = bv[he];
    float a0 = bvv, a1 = bvv, a2 = bvv, a3 = bvv;
    #pragma unroll 8
    for (int d = 0; d < DM; ++d) {
        float w = wv[(size_t)d*(NH*DH) + he];
        a0 = fmaf(x0[d],           w, a0);
        a1 = fmaf(x0[d +   NH*DM], w, a1);
        a2 = fmaf(x0[d + 2*NH*DM], w, a2);
        a3 = fmaf(x0[d + 3*NH*DM], w, a3);
    }
    g_o[(size_t)(n0+0)*(NH*DH) + he] = a0;
    g_o[(size_t)(n0+1)*(NH*DH) + he] = a1;
    g_o[(size_t)(n0+2)*(NH*DH) + he] = a2;
    g_o[(size_t)(n0+3)*(NH*DH) + he] = a3;
}

// ------------------------------ proj2 + LN (fused) ---------------------------
// grid (NB), block 768. xa = o@wo + bo; y = LN(xa).
__global__ void k_proj2ln(const float* __restrict__ wo, const float* __restrict__ bo,
                          const float* __restrict__ ln_s, const float* __restrict__ ln_b) {
    __shared__ float o_s[NH*DH];
    __shared__ float red[768];
    int n = blockIdx.x, t = threadIdx.x;
    o_s[t] = g_o[(size_t)n*(NH*DH) + t];
    __syncthreads();
    float a = bo[t];
    #pragma unroll 8
    for (int he = 0; he < NH*DH; ++he) a = fmaf(o_s[he], wo[(size_t)he*DM + t], a);
    g_xa[(size_t)n*DM + t] = a;
    // LayerNorm across the 768 threads
    red[t] = a; __syncthreads();
    if (t < 256) red[t] = red[t] + red[t+256] + red[t+512];
    __syncthreads();
    for (int s = 128; s > 0; s >>= 1) { if (t < s) red[t] += red[t+s]; __syncthreads(); }
    float mu = red[0] * (1.f/DM);
    __syncthreads();
    float dd = a - mu;
    red[t] = dd*dd; __syncthreads();
    if (t < 256) red[t] = red[t] + red[t+256] + red[t+512];
    __syncthreads();
    for (int s = 128; s > 0; s >>= 1) { if (t < s) red[t] += red[t+s]; __syncthreads(); }
    float rstd = rsqrtf(red[0] * (1.f/DM) + 1e-6f);
    g_y[(size_t)n*DM + t] = dd * rstd * ln_s[t] + ln_b[t];
}

// ------------------------------ MLP1: h1 = gelu(y@w1 + b1) (4-batch) ---------
// grid (12, 8), block 256. Thread: column k, 4 batches via 2 f32x2 accs.
__global__ void map_mlp1(const float* __restrict__ w1, const float* __restrict__ b1) {
    __shared__ ull y2a[DM], y2b[DM];    // 12 KB
    int nb = blockIdx.y, bj = blockIdx.x, t = threadIdx.x;
    int n0 = nb*4;
    for (int i = t; i < DM; i += 256) {
        y2a[i] = pk2(g_y[(size_t)(n0+0)*DM + i], g_y[(size_t)(n0+1)*DM + i]);
        y2b[i] = pk2(g_y[(size_t)(n0+2)*DM + i], g_y[(size_t)(n0+3)*DM + i]);
    }
    __syncthreads();
    int k = bj*256 + t;
    float b1v = b1[k];
    ull acc0 = pk2(b1v, b1v), acc1 = pk2(b1v, b1v);
    #pragma unroll 8
    for (int d = 0; d < DM; ++d) {
        float w = w1[(size_t)d*MLPD + k];
        ull wp = pk2(w, w);
        fma2(acc0, y2a[d], wp);
        fma2(acc1, y2b[d], wp);
    }
    float v0, v1, v2, v3;
    up2(acc0, v0, v1); up2(acc1, v2, v3);
    g_h1[(size_t)(n0+0)*MLPD + k] = gelu_f(v0);
    g_h1[(size_t)(n0+1)*MLPD + k] = gelu_f(v1);
    g_h1[(size_t)(n0+2)*MLPD + k] = gelu_f(v2);
    g_h1[(size_t)(n0+3)*MLPD + k] = gelu_f(v3);
}

// ------------------------------ MLP2 partial: K-split 4, 4-batch -------------
// grid (3, 8, 4), block 256. Thread: column d, 4 batches, K-chunk of 768.
__global__ void k_mlp2p(const float* __restrict__ w2) {
    __shared__ ull h2a[MLPD/4], h2b[MLPD/4];   // 12 KB
    int nb = blockIdx.y, bj = blockIdx.x, kc = blockIdx.z, t = threadIdx.x;
    int n0 = nb*4;
    for (int i = t; i < MLPD/4; i += 256) {
        h2a[i] = pk2(g_h1[(size_t)(n0+0)*MLPD + kc*(MLPD/4) + i],
                     g_h1[(size_t)(n0+1)*MLPD + kc*(MLPD/4) + i]);
        h2b[i] = pk2(g_h1[(size_t)(n0+2)*MLPD + kc*(MLPD/4) + i],
                     g_h1[(size_t)(n0+3)*MLPD + kc*(MLPD/4) + i]);
    }
    __syncthreads();
    int d = bj*256 + t;
    ull acc0 = 0ULL, acc1 = 0ULL;
    #pragma unroll 8
    for (int k = 0; k < MLPD/4; ++k) {
        float w = w2[(size_t)(kc*(MLPD/4) + k)*DM + d];
        ull wp = pk2(w, w);
        fma2(acc0, h2a[k], wp);
        fma2(acc1, h2b[k], wp);
    }
    float v0, v1, v2, v3;
    up2(acc0, v0, v1); up2(acc1, v2, v3);
    g_mp[((size_t)kc*NB + n0+0)*DM + d] = v0;
    g_mp[((size_t)kc*NB + n0+1)*DM + d] = v1;
    g_mp[((size_t)kc*NB + n0+2)*DM + d] = v2;
    g_mp[((size_t)kc*NB + n0+3)*DM + d] = v3;
}

// ------------------------------ final ----------------------------------------
// grid (3, NB), block 256.
__global__ void k_final(const float* __restrict__ b2, float* __restrict__ out) {
    int d = blockIdx.x*256 + threadIdx.x, n = blockIdx.y;
    float a = g_xa[(size_t)n*DM + d] + b2[d];
    #pragma unroll
    for (int kc = 0; kc < 4; ++kc)
        a += g_mp[((size_t)kc*NB + n)*DM + d];
    out[(size_t)n*DM + d] = a;
}

// ------------------------------ launcher -------------------------------------
extern "C" void kernel_launch(void* const* d_in, const int* in_sizes, int n_in,
                              void* d_out, int out_size) {
    const float* x     = (const float*)d_in[0];
    const float* probe = (const float*)d_in[1];
    const float* wq    = (const float*)d_in[2];
    const float* bq    = (const float*)d_in[3];
    const float* wk    = (const float*)d_in[4];
    const float* wv    = (const float*)d_in[6];
    const float* bv    = (const float*)d_in[7];
    const float* wo    = (const float*)d_in[8];
    const float* bo    = (const float*)d_in[9];
    const float* ln_s  = (const float*)d_in[10];
    const float* ln_b  = (const float*)d_in[11];
    const float* w1    = (const float*)d_in[12];
    const float* b1    = (const float*)d_in[13];
    const float* w2    = (const float*)d_in[14];
    const float* b2    = (const float*)d_in[15];
    float* out = (float*)d_out;

    k_qp<<<4, DM>>>(probe, wq);                            // 1
    prep_wkq<<<(NH*DM + 255)/256, 256>>>(wk, bq);          // 2
    k_logits<<<dim3(NCH, NB), 256>>>(x);                   // 3
    k_xbar<<<dim3(NCH, NB), 384>>>(x);                     // 4 <- profiled
    k_merge<<<dim3(NH, NB), 256>>>();                      // 5
    k_proj1<<<dim3(3, 8), 256>>>(wv, bv);                  // 6
    k_proj2ln<<<NB, 768>>>(wo, bo, ln_s, ln_b);            // 7
    map_mlp1<<<dim3(12, 8), 256>>>(w1, b1);                // 8
    k_mlp2p<<<dim3(3, 8, 4), 256>>>(w2);                   // 9
    k_final<<<dim3(3, NB), 256>>>(b2, out);                // 10
}

// round 16
// speedup vs baseline: 1.2333x; 1.2333x over previous
#include <cuda_runtime.h>
#include <math.h>

typedef unsigned long long ull;

// ---------------------------------------------------------------------------
// MAPHead: probe-attention pooling + MLP. N=32, L=4096, D=768, H=12, MLP=3072.
//   logits[n,h,l] = x[n,l,:] . wkq[:,h]      (pass 1, f32x2 head pairs, 2-row;
//                                             bk.q const dropped: softmax-inv)
//   k_logits emits per-chunk (m,sumexp)      (fused normalizer, parallel tail)
//   xbar[n,h,:] = sum_l softmax * x[n,l,:]   (pass 2, f32x2, 8-wide LDG batch)
//   o -> xa+LN (fused) -> MLP on [32,768]    (epilogue GEMVs, mlp2 K-split)
// ---------------------------------------------------------------------------

#define NB   32
#define LSEQ 4096
#define DM   768
#define NH   12
#define DH   64
#define MLPD 3072
#define NCH  16                 // 256-row chunks (pass 1 & 2)

__device__ __forceinline__ ull pk2(float a, float b) {
    ull r; asm("mov.b64 %0,{%1,%2};" : "=l"(r) : "f"(a), "f"(b)); return r;
}
__device__ __forceinline__ void up2(ull v, float& a, float& b) {
    asm("mov.b64 {%0,%1},%2;" : "=f"(a), "=f"(b) : "l"(v));
}
__device__ __forceinline__ void fma2(ull& acc, ull a, ull b) {
    asm("fma.rn.f32x2 %0,%1,%2,%0;" : "+l"(acc) : "l"(a), "l"(b));
}
__device__ __forceinline__ ull add2(ull a, ull b) {
    ull r; asm("add.rn.f32x2 %0,%1,%2;" : "=l"(r) : "l"(a), "l"(b)); return r;
}

// ------------------------------ scratch -------------------------------------
__device__ float  g_qp[4*DM];                         // probe@wq d-slice partials
__device__ float2 g_wkq2[6*DM];                       // [hp][d] head pairs
__device__ float  g_logits[(size_t)NB*NH*LSEQ];
__device__ float2 g_cms[NB*NCH*NH];                   // per-chunk (m, sumexp)
__device__ ull    g_part[(size_t)NB*NCH*NH*(DM/2)];   // chunk partial xbar
__device__ float  g_xbar[NB*NH*DM];
__device__ float  g_o[NB*NH*DH];
__device__ float  g_xa[NB*DM];
__device__ float  g_y[NB*DM];
__device__ float  g_h1[NB*MLPD];
__device__ float  g_mp[4*NB*DM];                      // mlp2 K-split partials

// ------------------------------ prep 1: qp[s][he] = probe_s . wq_s -----------
// grid 4 (d-slices of 192), block 768 (he). wq[d*768+he]: coalesced.
__global__ void k_qp(const float* __restrict__ probe,
                     const float* __restrict__ wq) {
    __shared__ float ps[192];
    int s = blockIdx.x, t = threadIdx.x;
    if (t < 192) ps[t] = probe[s*192 + t];
    __syncthreads();
    float acc = 0.f;
    const float* wp = wq + (size_t)(s*192)*(NH*DH) + t;
    #pragma unroll 8
    for (int d = 0; d < 192; ++d) acc = fmaf(ps[d], wp[(size_t)d*(NH*DH)], acc);
    g_qp[s*DM + t] = acc;
}

// ------------------------------ prep 2: wkq (qvec fused, head-pair packed) ---
__global__ void prep_wkq(const float* __restrict__ wk, const float* __restrict__ bq) {
    __shared__ float qv[NH*DH];
    int t = threadIdx.x;
    for (int i = t; i < NH*DH; i += 256)
        qv[i] = (g_qp[i] + g_qp[DM + i] + g_qp[2*DM + i] + g_qp[3*DM + i]
                 + bq[i]) * 0.125f;
    __syncthreads();
    int idx = blockIdx.x*256 + t;
    if (idx < NH*DM) {
        int d = idx / NH, h = idx - d*NH;
        float acc = 0.f;
        const float* w = wk + (size_t)d*(NH*DH) + h*DH;
        const float* q = qv + h*DH;
        #pragma unroll
        for (int e = 0; e < DH; ++e) acc = fmaf(w[e], q[e], acc);
        ((float*)g_wkq2)[(((h>>1)*DM) + d)*2 + (h&1)] = acc;
    }
}

// ------------------------------ pass 1: logits + chunk (m,s) -----------------
// grid (NCH, NB), block 256 (8 warps). Warp: 32 rows, 2 at a time (R11-proven).
// Tail: 192 threads (16 per head), shfl-reduced (m, sumexp).
__global__ void __launch_bounds__(256, 4)
k_logits(const float* __restrict__ x) {
    __shared__ float2 wks[6*DM];     // 36 KB
    const int t = threadIdx.x, lane = t & 31, w = t >> 5;
    const int n = blockIdx.y;
    const int row0 = blockIdx.x*256 + w*32;

    for (int i = t; i < 6*DM/2; i += 256)
        ((float4*)wks)[i] = ((const float4*)g_wkq2)[i];
    __syncthreads();

    for (int rb = 0; rb < 32; rb += 2) {
        const float* x0 = x + ((size_t)n*LSEQ + row0 + rb)*DM + lane;
        const float* x1 = x0 + DM;
        ull a0[6], a1[6];
        #pragma unroll
        for (int hp = 0; hp < 6; ++hp) { a0[hp] = 0ULL; a1[hp] = 0ULL; }

        #pragma unroll 4
        for (int j = 0; j < 24; ++j) {
            float u = x0[j*32];
            float v = x1[j*32];
            ull U = pk2(u, u), V = pk2(v, v);
            #pragma unroll
            for (int hp = 0; hp < 6; ++hp) {
                ull wv = *(const ull*)(wks + hp*DM + j*32 + lane);
                fma2(a0[hp], U, wv);
                fma2(a1[hp], V, wv);
            }
        }

        // packed butterfly reduce: 2 SHFL + 1 ADD2 per (hp, step)
        #pragma unroll
        for (int off = 16; off; off >>= 1)
            #pragma unroll
            for (int hp = 0; hp < 6; ++hp) {
                a0[hp] = add2(a0[hp], __shfl_xor_sync(0xffffffffu, a0[hp], off));
                a1[hp] = add2(a1[hp], __shfl_xor_sync(0xffffffffu, a1[hp], off));
            }

        if (lane < 2) {
            int l = row0 + rb + lane;
            float fr[NH];
            #pragma unroll
            for (int hp = 0; hp < 6; ++hp) {
                ull a = (lane == 0) ? a0[hp] : a1[hp];
                up2(a, fr[2*hp], fr[2*hp+1]);
            }
            #pragma unroll
            for (int h = 0; h < NH; ++h)
                g_logits[((size_t)n*NH + h)*LSEQ + l] = fr[h];
        }
    }

    // tail: per-chunk (m, sumexp), 16 threads per head, shfl-reduced
    __syncthreads();
    if (t < 192) {
        int g = t >> 4, i = t & 15;
        const float* lp = g_logits + ((size_t)n*NH + g)*LSEQ + blockIdx.x*256;
        float m = -1e30f;
        #pragma unroll
        for (int k = 0; k < 16; ++k) m = fmaxf(m, lp[i + k*16]);
        #pragma unroll
        for (int off = 8; off; off >>= 1)
            m = fmaxf(m, __shfl_xor_sync(0xffffffffu, m, off));
        float s = 0.f;
        #pragma unroll
        for (int k = 0; k < 16; ++k) s += __expf(lp[i + k*16] - m);
        #pragma unroll
        for (int off = 8; off; off >>= 1)
            s += __shfl_xor_sync(0xffffffffu, s, off);
        if (i == 0)
            g_cms[((size_t)n*NCH + blockIdx.x)*NH + g] = make_float2(m, s);
    }
}

// ------------------------------ pass 2: xbar (8-wide LDG batch) --------------
// grid (NCH, NB), block 384. Thread owns 2 cols; acc[12]; 8 outstanding LDG.64.
__global__ void __launch_bounds__(384)
k_xbar(const float* __restrict__ x) {
    __shared__ ull   p2s[NH*256];    // 24 KB
    __shared__ float Ms[NH], Is[NH];
    const int t = threadIdx.x, s = blockIdx.x, n = blockIdx.y;

    if (t < NH) {
        float M = -1e30f;
        #pragma unroll
        for (int c = 0; c < NCH; ++c)
            M = fmaxf(M, g_cms[((size_t)n*NCH + c)*NH + t].x);
        float S = 0.f;
        #pragma unroll
        for (int c = 0; c < NCH; ++c) {
            float2 ms = g_cms[((size_t)n*NCH + c)*NH + t];
            S += __expf(ms.x - M) * ms.y;
        }
        Ms[t] = M; Is[t] = 1.f / S;
    }
    __syncthreads();

    for (int i = t; i < NH*256; i += 384) {
        int h = i >> 8, r = i & 255;
        float lg = g_logits[((size_t)n*NH + h)*LSEQ + s*256 + r];
        float p = __expf(lg - Ms[h]) * Is[h];
        p2s[i] = pk2(p, p);
    }
    __syncthreads();

    ull acc[NH];
    #pragma unroll
    for (int h = 0; h < NH; ++h) acc[h] = 0ULL;

    const ull* xq = (const ull*)(x + ((size_t)n*LSEQ + s*256)*DM) + t;

    for (int r = 0; r < 256; r += 8) {
        ull xv[8];
        #pragma unroll
        for (int i = 0; i < 8; ++i)
            xv[i] = xq[(size_t)(r+i)*(DM/2)];
        #pragma unroll
        for (int h = 0; h < NH; ++h) {
            const ulonglong2* pp = (const ulonglong2*)(p2s + h*256 + r);
            ulonglong2 p01 = pp[0];
            ulonglong2 p23 = pp[1];
            ulonglong2 p45 = pp[2];
            ulonglong2 p67 = pp[3];
            fma2(acc[h], p01.x, xv[0]);
            fma2(acc[h], p01.y, xv[1]);
            fma2(acc[h], p23.x, xv[2]);
            fma2(acc[h], p23.y, xv[3]);
            fma2(acc[h], p45.x, xv[4]);
            fma2(acc[h], p45.y, xv[5]);
            fma2(acc[h], p67.x, xv[6]);
            fma2(acc[h], p67.y, xv[7]);
        }
    }
    #pragma unroll
    for (int h = 0; h < NH; ++h)
        g_part[(((size_t)(n*NCH + s)*NH) + h)*(DM/2) + t] = acc[h];
}

// ------------------------------ merge -> xbar[n][h][d] -----------------------
__global__ void k_merge() {
    int h = blockIdx.x, n = blockIdx.y, t = threadIdx.x;
    const float* pf = (const float*)g_part;
    #pragma unroll
    for (int j = 0; j < 3; ++j) {
        int d = j*256 + t;
        float a = 0.f;
        #pragma unroll
        for (int s = 0; s < NCH; ++s)
            a += pf[(((size_t)(n*NCH + s)*NH) + h)*DM + d];
        g_xbar[((size_t)n*NH + h)*DM + d] = a;
    }
}

// ------------------------------ proj1: o = xbar@wv + bv ----------------------
// grid (3, NB), block 256.
__global__ void k_proj1(const float* __restrict__ wv, const float* __restrict__ bv) {
    int n = blockIdx.y, he = blockIdx.x*256 + threadIdx.x;
    int h = he >> 6;
    const float* xh = g_xbar + ((size_t)n*NH + h)*DM;
    float a = bv[he];
    #pragma unroll 8
    for (int d = 0; d < DM; ++d) a = fmaf(xh[d], wv[(size_t)d*(NH*DH) + he], a);
    g_o[(size_t)n*(NH*DH) + he] = a;
}

// ------------------------------ proj2 + LN (fused) ---------------------------
// grid (NB), block 768. xa = o@wo + bo; y = LN(xa).
__global__ void k_proj2ln(const float* __restrict__ wo, const float* __restrict__ bo,
                          const float* __restrict__ ln_s, const float* __restrict__ ln_b) {
    __shared__ float o_s[NH*DH];
    __shared__ float red[768];
    int n = blockIdx.x, t = threadIdx.x;
    o_s[t] = g_o[(size_t)n*(NH*DH) + t];
    __syncthreads();
    float a = bo[t];
    #pragma unroll 8
    for (int he = 0; he < NH*DH; ++he) a = fmaf(o_s[he], wo[(size_t)he*DM + t], a);
    g_xa[(size_t)n*DM + t] = a;
    // LayerNorm across the 768 threads
    red[t] = a; __syncthreads();
    if (t < 256) red[t] = red[t] + red[t+256] + red[t+512];
    __syncthreads();
    for (int s = 128; s > 0; s >>= 1) { if (t < s) red[t] += red[t+s]; __syncthreads(); }
    float mu = red[0] * (1.f/DM);
    __syncthreads();
    float dd = a - mu;
    red[t] = dd*dd; __syncthreads();
    if (t < 256) red[t] = red[t] + red[t+256] + red[t+512];
    __syncthreads();
    for (int s = 128; s > 0; s >>= 1) { if (t < s) red[t] += red[t+s]; __syncthreads(); }
    float rstd = rsqrtf(red[0] * (1.f/DM) + 1e-6f);
    g_y[(size_t)n*DM + t] = dd * rstd * ln_s[t] + ln_b[t];
}

// ------------------------------ MLP1: h1 = gelu(y@w1 + b1) -------------------
// grid (12, NB), block 256.
__global__ void map_mlp1(const float* __restrict__ w1, const float* __restrict__ b1) {
    __shared__ float y_s[DM];
    int n = blockIdx.y, bj = blockIdx.x, t = threadIdx.x;
    for (int j = 0; j < 3; ++j) y_s[j*256 + t] = g_y[(size_t)n*DM + j*256 + t];
    __syncthreads();
    int k = bj*256 + t;
    float a = b1[k];
    #pragma unroll 8
    for (int d = 0; d < DM; ++d) a = fmaf(y_s[d], w1[(size_t)d*MLPD + k], a);
    float u = 0.7978845608028654f * (a + 0.044715f * a * a * a);
    g_h1[(size_t)n*MLPD + k] = 0.5f * a * (1.f + tanhf(u));
}

// ------------------------------ MLP2 partial: K-split 4 ----------------------
// grid (3, NB, 4), block 256.
__global__ void k_mlp2p(const float* __restrict__ w2) {
    __shared__ float h1_s[MLPD/4];
    int n = blockIdx.y, bj = blockIdx.x, kc = blockIdx.z, t = threadIdx.x;
    for (int i = t; i < MLPD/4; i += 256)
        h1_s[i] = g_h1[(size_t)n*MLPD + kc*(MLPD/4) + i];
    __syncthreads();
    int d = bj*256 + t;
    float a = 0.f;
    #pragma unroll 8
    for (int k = 0; k < MLPD/4; ++k)
        a = fmaf(h1_s[k], w2[(size_t)(kc*(MLPD/4) + k)*DM + d], a);
    g_mp[((size_t)kc*NB + n)*DM + d] = a;
}

// ------------------------------ final ----------------------------------------
// grid (3, NB), block 256.
__global__ void k_final(const float* __restrict__ b2, float* __restrict__ out) {
    int d = blockIdx.x*256 + threadIdx.x, n = blockIdx.y;
    float a = g_xa[(size_t)n*DM + d] + b2[d];
    #pragma unroll
    for (int kc = 0; kc < 4; ++kc)
        a += g_mp[((size_t)kc*NB + n)*DM + d];
    out[(size_t)n*DM + d] = a;
}

// ------------------------------ launcher -------------------------------------
extern "C" void kernel_launch(void* const* d_in, const int* in_sizes, int n_in,
                              void* d_out, int out_size) {
    const float* x     = (const float*)d_in[0];
    const float* probe = (const float*)d_in[1];
    const float* wq    = (const float*)d_in[2];
    const float* bq    = (const float*)d_in[3];
    const float* wk    = (const float*)d_in[4];
    const float* wv    = (const float*)d_in[6];
    const float* bv    = (const float*)d_in[7];
    const float* wo    = (const float*)d_in[8];
    const float* bo    = (const float*)d_in[9];
    const float* ln_s  = (const float*)d_in[10];
    const float* ln_b  = (const float*)d_in[11];
    const float* w1    = (const float*)d_in[12];
    const float* b1    = (const float*)d_in[13];
    const float* w2    = (const float*)d_in[14];
    const float* b2    = (const float*)d_in[15];
    float* out = (float*)d_out;

    k_qp<<<4, DM>>>(probe, wq);                            // 1
    prep_wkq<<<(NH*DM + 255)/256, 256>>>(wk, bq);          // 2
    k_logits<<<dim3(NCH, NB), 256>>>(x);                   // 3
    k_xbar<<<dim3(NCH, NB), 384>>>(x);                     // 4 <- profiled
    k_merge<<<dim3(NH, NB), 256>>>();                      // 5
    k_proj1<<<dim3(3, NB), 256>>>(wv, bv);                 // 6
    k_proj2ln<<<NB, 768>>>(wo, bo, ln_s, ln_b);            // 7
    map_mlp1<<<dim3(MLPD/256, NB), 256>>>(w1, b1);         // 8
    k_mlp2p<<<dim3(3, NB, 4), 256>>>(w2);                  // 9
    k_final<<<dim3(3, NB), 256>>>(b2, out);                // 10
}